// round 3
// baseline (speedup 1.0000x reference)
#include <cuda_runtime.h>

typedef unsigned long long ULL;

__device__ __forceinline__ void fma2(ULL& d, ULL a, ULL b) {
    asm("fma.rn.f32x2 %0, %1, %2, %0;" : "+l"(d) : "l"(a), "l"(b));
}
__device__ __forceinline__ float f2sum(ULL v) {
    float x, y;
    asm("mov.b64 {%0,%1}, %2;" : "=f"(x), "=f"(y) : "l"(v));
    return x + y;
}
__device__ __forceinline__ float sigf(float x) { return 1.f / (1.f + expf(-x)); }

// ---------------- scratch (static device buffers; no allocation) -------------
__device__ float g_x[32768 * 256];          // embedded input          (33.5 MB)
__device__ float g_xg[(size_t)32768 * 2048];// input-proj gates buffer (268 MB, reused per layer)
__device__ float g_out0[32768 * 512];       // layer0 output           (67 MB)
__device__ float g_out1[32768 * 512];       // layer1 output           (67 MB)
__device__ float g_h[2 * 2 * 128 * 256];    // h ping-pong [ping][dir][b][k]
__device__ float g_c[2 * 128 * 256];        // c state     [dir][b][k]
__device__ float g_feats[(size_t)32768 * 22];
__device__ float g_nll[128];

// ---------------- embedding gather ----------------
__global__ void embed_k(const float* __restrict__ emb, const int* __restrict__ words) {
    int idx = blockIdx.x * 256 + threadIdx.x;   // 32768*256 total
    int i = idx >> 8, e = idx & 255;
    int w = words[i];
    g_x[idx] = emb[(size_t)w * 256 + e];
}

// ---------------- input-projection GEMM -------------------------------------
// C[32768][2048] = A[32768][K] * W[2048][K]^T + (b_ih + b_hh)
// block tile 128(m) x 64(n), 256 threads, thread frag 8m x 4n, f32x2 over k-pairs
template <int K>
__global__ void __launch_bounds__(256) gemm_xg_k(const float* __restrict__ W,
                                                 const float* __restrict__ bi,
                                                 const float* __restrict__ bh) {
    const float* A = (K == 256) ? g_x : g_out0;
    __shared__ float As[2][128][18];   // rows padded to 18 floats (9 ull, odd -> conflict-free)
    __shared__ float Ws[2][64][18];

    int tid = threadIdx.x;
    int ty = tid >> 4, tx = tid & 15;
    const float* Ab = A + (size_t)blockIdx.y * 128 * K;
    const float* Wb = W + (size_t)blockIdx.x * 64 * K;

    int arow = tid >> 1, acol = (tid & 1) * 8;
    int wrow = tid >> 2, wcol = (tid & 3) * 4;

    float4 a0, a1, w0;
    a0 = *(const float4*)(Ab + arow * K + acol);
    a1 = *(const float4*)(Ab + arow * K + acol + 4);
    w0 = *(const float4*)(Wb + wrow * K + wcol);
    *(float2*)&As[0][arow][acol + 0] = make_float2(a0.x, a0.y);
    *(float2*)&As[0][arow][acol + 2] = make_float2(a0.z, a0.w);
    *(float2*)&As[0][arow][acol + 4] = make_float2(a1.x, a1.y);
    *(float2*)&As[0][arow][acol + 6] = make_float2(a1.z, a1.w);
    *(float2*)&Ws[0][wrow][wcol + 0] = make_float2(w0.x, w0.y);
    *(float2*)&Ws[0][wrow][wcol + 2] = make_float2(w0.z, w0.w);
    __syncthreads();

    ULL acc[8][4] = {};
    const int NC = K / 16;

    for (int c = 0; c < NC; ++c) {
        int buf = c & 1;
        if (c + 1 < NC) {
            const float* Ap = Ab + arow * K + (c + 1) * 16 + acol;
            a0 = *(const float4*)(Ap);
            a1 = *(const float4*)(Ap + 4);
            w0 = *(const float4*)(Wb + wrow * K + (c + 1) * 16 + wcol);
        }
#pragma unroll
        for (int kp = 0; kp < 8; ++kp) {
            ULL av[8], wv[4];
#pragma unroll
            for (int i = 0; i < 8; ++i) av[i] = *(const ULL*)&As[buf][ty * 8 + i][kp * 2];
#pragma unroll
            for (int j = 0; j < 4; ++j) wv[j] = *(const ULL*)&Ws[buf][tx + j * 16][kp * 2];
#pragma unroll
            for (int i = 0; i < 8; ++i)
#pragma unroll
                for (int j = 0; j < 4; ++j) fma2(acc[i][j], av[i], wv[j]);
        }
        if (c + 1 < NC) {
            int nb = buf ^ 1;
            *(float2*)&As[nb][arow][acol + 0] = make_float2(a0.x, a0.y);
            *(float2*)&As[nb][arow][acol + 2] = make_float2(a0.z, a0.w);
            *(float2*)&As[nb][arow][acol + 4] = make_float2(a1.x, a1.y);
            *(float2*)&As[nb][arow][acol + 6] = make_float2(a1.z, a1.w);
            *(float2*)&Ws[nb][wrow][wcol + 0] = make_float2(w0.x, w0.y);
            *(float2*)&Ws[nb][wrow][wcol + 2] = make_float2(w0.z, w0.w);
            __syncthreads();
        }
    }

#pragma unroll
    for (int i = 0; i < 8; ++i) {
        size_t m = (size_t)blockIdx.y * 128 + ty * 8 + i;
#pragma unroll
        for (int j = 0; j < 4; ++j) {
            int n = blockIdx.x * 64 + tx + j * 16;
            g_xg[m * 2048 + n] = f2sum(acc[i][j]) + bi[n] + bh[n];
        }
    }
}

// ---------------- zero h (both pings) and c ----------------
__global__ void init_hc() {
    int i = blockIdx.x * 256 + threadIdx.x;   // 512 blocks * 256 = 131072
    g_h[i] = 0.f;
    if (i < 2 * 128 * 256) g_c[i] = 0.f;
}

// ---------------- fused LSTM step (both directions) --------------------------
// 128 blocks: dir(2) x batch-chunk(4 of 32) x unit-chunk(16 of 16)
// 128 threads: thread = 4 batches x 1 unit (its 4 gate rows i,f,g,o)
#define STEP_SMEM ((32 + 64) * 258 * 4)
__global__ void __launch_bounds__(128) lstm_step(const float* __restrict__ whh, int layer, int t) {
    extern __shared__ float sm[];
    float* hs = sm;             // [32][258]  (129 ull per row: odd -> conflict-free)
    float* ws = sm + 32 * 258;  // [64][258]  row = gt*16 + u

    int bx = blockIdx.x;
    int dir = bx & 1, bch = (bx >> 1) & 3, uch = bx >> 3;
    int tid = threadIdx.x;
    int td = dir ? 255 - t : t;

    const float* hin = g_h + (t & 1) * (2 * 128 * 256);
    float* hout = g_h + ((t & 1) ^ 1) * (2 * 128 * 256);
    float* ob = layer ? g_out1 : g_out0;

    const float* hb = hin + (dir * 128 + bch * 32) * 256;
#pragma unroll 4
    for (int r = 0; r < 32; ++r) {
        int q = r * 128 + tid;
        int row = q >> 7, c2 = q & 127;
        *(float2*)&hs[row * 258 + c2 * 2] = *(const float2*)&hb[row * 256 + c2 * 2];
    }
    const float* wb = whh + (size_t)dir * 1024 * 256;
#pragma unroll 4
    for (int r = 0; r < 64; ++r) {
        int q = r * 128 + tid;
        int wrow = q >> 7, c2 = q & 127;
        int gt = wrow >> 4, u = wrow & 15;
        *(float2*)&ws[wrow * 258 + c2 * 2] =
            *(const float2*)&wb[(size_t)(gt * 256 + uch * 16 + u) * 256 + c2 * 2];
    }
    __syncthreads();

    int u = tid & 15, b4 = tid >> 4;
    int uu = uch * 16 + u;
    int b0 = bch * 32 + b4 * 4;

    ULL acc[4][4] = {};
    const float* hp[4];
    const float* wp[4];
#pragma unroll
    for (int j = 0; j < 4; ++j) hp[j] = &hs[(b4 * 4 + j) * 258];
#pragma unroll
    for (int g = 0; g < 4; ++g) wp[g] = &ws[(g * 16 + u) * 258];

#pragma unroll 4
    for (int kp = 0; kp < 128; ++kp) {
        ULL hv[4], wv[4];
#pragma unroll
        for (int j = 0; j < 4; ++j) hv[j] = *(const ULL*)(hp[j] + kp * 2);
#pragma unroll
        for (int g = 0; g < 4; ++g) wv[g] = *(const ULL*)(wp[g] + kp * 2);
#pragma unroll
        for (int g = 0; g < 4; ++g)
#pragma unroll
            for (int j = 0; j < 4; ++j) fma2(acc[g][j], hv[j], wv[g]);
    }

#pragma unroll
    for (int j = 0; j < 4; ++j) {
        int b = b0 + j;
        size_t xbase = ((size_t)b * 256 + td) * 2048 + dir * 1024 + uu;
        float gi = f2sum(acc[0][j]) + g_xg[xbase];
        float gf = f2sum(acc[1][j]) + g_xg[xbase + 256];
        float gg = f2sum(acc[2][j]) + g_xg[xbase + 512];
        float go = f2sum(acc[3][j]) + g_xg[xbase + 768];
        int ci = (dir * 128 + b) * 256 + uu;
        float cn = sigf(gf) * g_c[ci] + sigf(gi) * tanhf(gg);
        float hn = sigf(go) * tanhf(cn);
        g_c[ci] = cn;
        hout[ci] = hn;
        ob[((size_t)b * 256 + td) * 512 + dir * 256 + uu] = hn;
    }
}

// ---------------- LayerNorm + output projection -------------------------------
__global__ void __launch_bounds__(128) lnfeats(const float* __restrict__ lng,
                                               const float* __restrict__ lnb,
                                               const float* __restrict__ wo,
                                               const float* __restrict__ bo) {
    __shared__ float row[512];
    __shared__ float red[10];
    int i = blockIdx.x, tid = threadIdx.x;
    float4 v = *(const float4*)&g_out1[(size_t)i * 512 + tid * 4];
    float s = v.x + v.y + v.z + v.w;
    float q = v.x * v.x + v.y * v.y + v.z * v.z + v.w * v.w;
#pragma unroll
    for (int o = 16; o; o >>= 1) {
        s += __shfl_xor_sync(0xffffffffu, s, o);
        q += __shfl_xor_sync(0xffffffffu, q, o);
    }
    int wid = tid >> 5, lane = tid & 31;
    if (!lane) { red[wid] = s; red[4 + wid] = q; }
    __syncthreads();
    if (!tid) {
        float S = red[0] + red[1] + red[2] + red[3];
        float Q = red[4] + red[5] + red[6] + red[7];
        float mu = S / 512.f;
        float var = Q / 512.f - mu * mu;
        red[8] = mu;
        red[9] = rsqrtf(var + 1e-5f);
    }
    __syncthreads();
    float mu = red[8], rs = red[9];
    int k = tid * 4;
    row[k + 0] = (v.x - mu) * rs * lng[k + 0] + lnb[k + 0];
    row[k + 1] = (v.y - mu) * rs * lng[k + 1] + lnb[k + 1];
    row[k + 2] = (v.z - mu) * rs * lng[k + 2] + lnb[k + 2];
    row[k + 3] = (v.w - mu) * rs * lng[k + 3] + lnb[k + 3];
    __syncthreads();
    for (int o = wid; o < 22; o += 4) {
        float a = 0.f;
        const float* wr = wo + o * 512;
        for (int k2 = lane; k2 < 512; k2 += 32) a += row[k2] * wr[k2];
#pragma unroll
        for (int off = 16; off; off >>= 1) a += __shfl_xor_sync(0xffffffffu, a, off);
        if (!lane) g_feats[(size_t)i * 22 + o] = a + bo[o];
    }
}

// ---------------- CRF forward + scores (one warp per batch) -------------------
__global__ void crf_k(const float* __restrict__ trans, const int* __restrict__ mask,
                      const int* __restrict__ tags) {
    __shared__ float tr[484];
    __shared__ float alpha[22];
    int b = blockIdx.x, j = threadIdx.x;
    for (int q = j; q < 484; q += 32) tr[q] = trans[q];
    const float* Fb = g_feats + (size_t)b * 256 * 22;
    __syncwarp();
    if (j < 22) alpha[j] = tr[20 * 22 + j] + Fb[j];
    __syncwarp();
    for (int t = 1; t < 256; ++t) {
        float aj = 0.f;
        if (j < 22) {
            float m = -1e30f;
#pragma unroll
            for (int i2 = 0; i2 < 22; ++i2) m = fmaxf(m, alpha[i2] + tr[i2 * 22 + j]);
            float sm = 0.f;
#pragma unroll
            for (int i2 = 0; i2 < 22; ++i2) sm += expf(alpha[i2] + tr[i2 * 22 + j] - m);
            aj = m + logf(sm) + Fb[t * 22 + j];
        }
        int mt = mask[b * 256 + t];
        __syncwarp();
        if (j < 22 && mt) alpha[j] = aj;
        __syncwarp();
    }
    float v = (j < 22) ? alpha[j] + tr[j * 22 + 21] : -1e30f;
    float m = v;
#pragma unroll
    for (int off = 16; off; off >>= 1) m = fmaxf(m, __shfl_xor_sync(0xffffffffu, m, off));
    float e = (j < 22) ? expf(v - m) : 0.f;
#pragma unroll
    for (int off = 16; off; off >>= 1) e += __shfl_xor_sync(0xffffffffu, e, off);
    float logZ = m + logf(e);

    const int* tg = tags + (size_t)b * 256;
    const int* mk = mask + b * 256;
    float emit = 0.f, trs = 0.f;
    int cnt = 0;
    for (int t = j; t < 256; t += 32) {
        if (mk[t]) {
            emit += Fb[t * 22 + tg[t]];
            cnt++;
            if (t >= 1) trs += tr[tg[t - 1] * 22 + tg[t]];
        }
    }
#pragma unroll
    for (int off = 16; off; off >>= 1) {
        emit += __shfl_xor_sync(0xffffffffu, emit, off);
        trs += __shfl_xor_sync(0xffffffffu, trs, off);
        cnt += __shfl_xor_sync(0xffffffffu, cnt, off);
    }
    if (!j) {
        trs += tr[20 * 22 + tg[0]];
        trs += tr[tg[cnt - 1] * 22 + 21];
        g_nll[b] = logZ - emit - trs;
    }
}

__global__ void reduce_nll(float* out) {
    int tid = threadIdx.x;  // 128
    float v = g_nll[tid];
#pragma unroll
    for (int off = 16; off; off >>= 1) v += __shfl_xor_sync(0xffffffffu, v, off);
    __shared__ float r[4];
    if (!(tid & 31)) r[tid >> 5] = v;
    __syncthreads();
    if (!tid) out[0] = (r[0] + r[1] + r[2] + r[3]) / 128.f;
}

// ---------------- launcher ----------------
extern "C" void kernel_launch(void* const* d_in, const int* in_sizes, int n_in,
                              void* d_out, int out_size) {
    const float* emb    = (const float*)d_in[0];
    const float* w_ih0  = (const float*)d_in[1];
    const float* w_hh0  = (const float*)d_in[2];
    const float* b_ih0  = (const float*)d_in[3];
    const float* b_hh0  = (const float*)d_in[4];
    const float* w_ih1  = (const float*)d_in[5];
    const float* w_hh1  = (const float*)d_in[6];
    const float* b_ih1  = (const float*)d_in[7];
    const float* b_hh1  = (const float*)d_in[8];
    const float* ln_g   = (const float*)d_in[9];
    const float* ln_b   = (const float*)d_in[10];
    const float* w_out  = (const float*)d_in[11];
    const float* b_out  = (const float*)d_in[12];
    const float* trans  = (const float*)d_in[13];
    const int* words    = (const int*)d_in[14];   // JAX default: int64 -> int32
    const int* mask     = (const int*)d_in[15];
    const int* tags     = (const int*)d_in[16];   // int32 (see above)
    float* out = (float*)d_out;

    cudaFuncSetAttribute(lstm_step, cudaFuncAttributeMaxDynamicSharedMemorySize, STEP_SMEM);

    embed_k<<<32768, 256>>>(emb, words);
    gemm_xg_k<256><<<dim3(32, 256), 256>>>(w_ih0, b_ih0, b_hh0);
    init_hc<<<512, 256>>>();
    for (int t = 0; t < 256; ++t)
        lstm_step<<<128, 128, STEP_SMEM>>>(w_hh0, 0, t);
    gemm_xg_k<512><<<dim3(32, 256), 256>>>(w_ih1, b_ih1, b_hh1);
    init_hc<<<512, 256>>>();
    for (int t = 0; t < 256; ++t)
        lstm_step<<<128, 128, STEP_SMEM>>>(w_hh1, 1, t);
    lnfeats<<<32768, 128>>>(ln_g, ln_b, w_out, b_out);
    crf_k<<<128, 32>>>(trans, mask, tags);
    reduce_nll<<<1, 128>>>(out);
}

// round 4
// speedup vs baseline: 1.2729x; 1.2729x over previous
#include <cuda_runtime.h>

typedef unsigned long long ULL;

__device__ __forceinline__ void fma2(ULL& d, ULL a, ULL b) {
    asm("fma.rn.f32x2 %0, %1, %2, %0;" : "+l"(d) : "l"(a), "l"(b));
}
__device__ __forceinline__ ULL f2add(ULL a, ULL b) {
    ULL d;
    asm("add.rn.f32x2 %0, %1, %2;" : "=l"(d) : "l"(a), "l"(b));
    return d;
}
__device__ __forceinline__ float f2sum(ULL v) {
    float x, y;
    asm("mov.b64 {%0,%1}, %2;" : "=f"(x), "=f"(y) : "l"(v));
    return x + y;
}
__device__ __forceinline__ float sigf(float x) { return 1.f / (1.f + expf(-x)); }

// ---------------- scratch (static device buffers; no allocation) -------------
__device__ float g_x[32768 * 256];          // embedded input
__device__ float g_xg[(size_t)32768 * 2048];// input-proj gates buffer (reused per layer)
__device__ float g_out0[32768 * 512];       // layer0 output
__device__ float g_out1[32768 * 512];       // layer1 output
__device__ float g_h[2 * 2 * 128 * 256];    // h ping-pong [ping][dir][b][k]
__device__ float g_feats[(size_t)32768 * 22];
__device__ float g_nll[128];
__device__ unsigned g_bar[8];               // group barriers (dir x bch)

// ---------------- embedding gather ----------------
__global__ void embed_k(const float* __restrict__ emb, const int* __restrict__ words) {
    int idx = blockIdx.x * 256 + threadIdx.x;
    int i = idx >> 8, e = idx & 255;
    int w = words[i];
    g_x[idx] = emb[(size_t)w * 256 + e];
}

// ---------------- input-projection GEMM (unchanged, passing) -----------------
template <int K>
__global__ void __launch_bounds__(256) gemm_xg_k(const float* __restrict__ W,
                                                 const float* __restrict__ bi,
                                                 const float* __restrict__ bh) {
    const float* A = (K == 256) ? g_x : g_out0;
    __shared__ float As[2][128][18];
    __shared__ float Ws[2][64][18];

    int tid = threadIdx.x;
    int ty = tid >> 4, tx = tid & 15;
    const float* Ab = A + (size_t)blockIdx.y * 128 * K;
    const float* Wb = W + (size_t)blockIdx.x * 64 * K;

    int arow = tid >> 1, acol = (tid & 1) * 8;
    int wrow = tid >> 2, wcol = (tid & 3) * 4;

    float4 a0, a1, w0;
    a0 = *(const float4*)(Ab + arow * K + acol);
    a1 = *(const float4*)(Ab + arow * K + acol + 4);
    w0 = *(const float4*)(Wb + wrow * K + wcol);
    *(float2*)&As[0][arow][acol + 0] = make_float2(a0.x, a0.y);
    *(float2*)&As[0][arow][acol + 2] = make_float2(a0.z, a0.w);
    *(float2*)&As[0][arow][acol + 4] = make_float2(a1.x, a1.y);
    *(float2*)&As[0][arow][acol + 6] = make_float2(a1.z, a1.w);
    *(float2*)&Ws[0][wrow][wcol + 0] = make_float2(w0.x, w0.y);
    *(float2*)&Ws[0][wrow][wcol + 2] = make_float2(w0.z, w0.w);
    __syncthreads();

    ULL acc[8][4] = {};
    const int NC = K / 16;

    for (int c = 0; c < NC; ++c) {
        int buf = c & 1;
        if (c + 1 < NC) {
            const float* Ap = Ab + arow * K + (c + 1) * 16 + acol;
            a0 = *(const float4*)(Ap);
            a1 = *(const float4*)(Ap + 4);
            w0 = *(const float4*)(Wb + wrow * K + (c + 1) * 16 + wcol);
        }
#pragma unroll
        for (int kp = 0; kp < 8; ++kp) {
            ULL av[8], wv[4];
#pragma unroll
            for (int i = 0; i < 8; ++i) av[i] = *(const ULL*)&As[buf][ty * 8 + i][kp * 2];
#pragma unroll
            for (int j = 0; j < 4; ++j) wv[j] = *(const ULL*)&Ws[buf][tx + j * 16][kp * 2];
#pragma unroll
            for (int i = 0; i < 8; ++i)
#pragma unroll
                for (int j = 0; j < 4; ++j) fma2(acc[i][j], av[i], wv[j]);
        }
        if (c + 1 < NC) {
            int nb = buf ^ 1;
            *(float2*)&As[nb][arow][acol + 0] = make_float2(a0.x, a0.y);
            *(float2*)&As[nb][arow][acol + 2] = make_float2(a0.z, a0.w);
            *(float2*)&As[nb][arow][acol + 4] = make_float2(a1.x, a1.y);
            *(float2*)&As[nb][arow][acol + 6] = make_float2(a1.z, a1.w);
            *(float2*)&Ws[nb][wrow][wcol + 0] = make_float2(w0.x, w0.y);
            *(float2*)&Ws[nb][wrow][wcol + 2] = make_float2(w0.z, w0.w);
            __syncthreads();
        }
    }

#pragma unroll
    for (int i = 0; i < 8; ++i) {
        size_t m = (size_t)blockIdx.y * 128 + ty * 8 + i;
#pragma unroll
        for (int j = 0; j < 4; ++j) {
            int n = blockIdx.x * 64 + tx + j * 16;
            g_xg[m * 2048 + n] = f2sum(acc[i][j]) + bi[n] + bh[n];
        }
    }
}

// ---------------- zero h pings + group barriers ----------------
__global__ void init_hc() {
    int i = blockIdx.x * 256 + threadIdx.x;   // 512*256 = 131072 = all of g_h
    g_h[i] = 0.f;
    if (i < 8) g_bar[i] = 0u;
}

// ---------------- persistent BiLSTM layer -------------------------------------
// 128 blocks: dir(2) x bch(4 of 32 batches) x uch(16 of 16 units); all resident.
// 256 threads: warp-group wg = tid>>7 splits K (128 each); within wg:
//   u = wtid&15 (unit), bg = wtid>>4 (8 groups x 4 batches).
// W_hh slice staged in smem ONCE; c lives in registers for the whole sequence.
// Cross-block sync: per-(dir,bch) group barrier over 16 blocks, monotonic counter.
#define PERS_SMEM ((64 * 258 + 32 * 258) * 4 + 128 * 16 * 8)
__global__ void __launch_bounds__(256) lstm_persist(const float* __restrict__ whh, int layer) {
    extern __shared__ float sm[];
    float* ws = sm;                      // [64][258] rows: g*16+u
    float* hs = sm + 64 * 258;           // [32][258]
    ULL* part = (ULL*)(sm + 96 * 258);   // [128][16] wg1 partial accumulators

    int bx = blockIdx.x;
    int dir = bx & 1, bch = (bx >> 1) & 3, uch = bx >> 3;
    int grp = bx & 7;                    // (dir, bch) group
    int tid = threadIdx.x;
    int wg = tid >> 7, wtid = tid & 127;
    int u = wtid & 15, bg = wtid >> 4;
    int uu = uch * 16 + u;
    int b0 = bch * 32 + bg * 4;

    // stage W_hh slice once: 64 rows (4 gates x 16 units) x 256 k
    const float* wb = whh + (size_t)dir * 1024 * 256;
#pragma unroll 4
    for (int r = 0; r < 32; ++r) {
        int q = r * 256 + tid;           // 8192 float2
        int wrow = q >> 7, cc = q & 127;
        int gt = wrow >> 4, uw = wrow & 15;
        *(float2*)&ws[wrow * 258 + cc * 2] =
            *(const float2*)&wb[(size_t)(gt * 256 + uch * 16 + uw) * 256 + cc * 2];
    }

    float creg[4] = {0.f, 0.f, 0.f, 0.f};
    float* ob = layer ? g_out1 : g_out0;
    const int kbase = wg * 128;

    for (int t = 0; t < 256; ++t) {
        int td = dir ? 255 - t : t;
        const float* hin = g_h + (t & 1) * (2 * 128 * 256);
        float* hout = g_h + ((t & 1) ^ 1) * (2 * 128 * 256);

        // stage h_{t-1} slice (32 batches x 256) — .cg to bypass stale L1
        const float* hb = hin + (dir * 128 + bch * 32) * 256;
#pragma unroll 4
        for (int r = 0; r < 16; ++r) {
            int q = r * 256 + tid;       // 4096 float2
            int row = q >> 7, cc = q & 127;
            *(float2*)&hs[row * 258 + cc * 2] = __ldcg((const float2*)&hb[row * 256 + cc * 2]);
        }
        __syncthreads();

        ULL acc[4][4] = {};
#pragma unroll 4
        for (int kp = 0; kp < 64; ++kp) {
            ULL hv[4], wv[4];
#pragma unroll
            for (int j = 0; j < 4; ++j)
                hv[j] = *(const ULL*)&hs[(bg * 4 + j) * 258 + kbase + kp * 2];
#pragma unroll
            for (int g = 0; g < 4; ++g)
                wv[g] = *(const ULL*)&ws[(g * 16 + u) * 258 + kbase + kp * 2];
#pragma unroll
            for (int g = 0; g < 4; ++g)
#pragma unroll
                for (int j = 0; j < 4; ++j) fma2(acc[g][j], hv[j], wv[g]);
        }

        if (wg == 1) {
#pragma unroll
            for (int g = 0; g < 4; ++g)
#pragma unroll
                for (int j = 0; j < 4; ++j) part[wtid * 16 + g * 4 + j] = acc[g][j];
        }
        __syncthreads();

        if (wg == 0) {
            const ULL* pp = &part[wtid * 16];
#pragma unroll
            for (int j = 0; j < 4; ++j) {
                int b = b0 + j;
                size_t xbase = ((size_t)b * 256 + td) * 2048 + dir * 1024 + uu;
                float gi = f2sum(f2add(acc[0][j], pp[0 * 4 + j])) + g_xg[xbase];
                float gf = f2sum(f2add(acc[1][j], pp[1 * 4 + j])) + g_xg[xbase + 256];
                float gg = f2sum(f2add(acc[2][j], pp[2 * 4 + j])) + g_xg[xbase + 512];
                float go = f2sum(f2add(acc[3][j], pp[3 * 4 + j])) + g_xg[xbase + 768];
                float cn = sigf(gf) * creg[j] + sigf(gi) * tanhf(gg);
                float hn = sigf(go) * tanhf(cn);
                creg[j] = cn;
                hout[(dir * 128 + b) * 256 + uu] = hn;
                ob[((size_t)b * 256 + td) * 512 + dir * 256 + uu] = hn;
            }
            __threadfence();
        }
        __syncthreads();

        // group barrier: 16 blocks of this (dir,bch) group; monotonic counter
        if (tid == 0) {
            atomicAdd(&g_bar[grp], 1u);
            unsigned tgt = 16u * (unsigned)(t + 1);
            while (atomicAdd(&g_bar[grp], 0u) < tgt) __nanosleep(64);
            __threadfence();
        }
        __syncthreads();
    }
}

// ---------------- LayerNorm + output projection -------------------------------
__global__ void __launch_bounds__(128) lnfeats(const float* __restrict__ lng,
                                               const float* __restrict__ lnb,
                                               const float* __restrict__ wo,
                                               const float* __restrict__ bo) {
    __shared__ float row[512];
    __shared__ float red[10];
    int i = blockIdx.x, tid = threadIdx.x;
    float4 v = *(const float4*)&g_out1[(size_t)i * 512 + tid * 4];
    float s = v.x + v.y + v.z + v.w;
    float q = v.x * v.x + v.y * v.y + v.z * v.z + v.w * v.w;
#pragma unroll
    for (int o = 16; o; o >>= 1) {
        s += __shfl_xor_sync(0xffffffffu, s, o);
        q += __shfl_xor_sync(0xffffffffu, q, o);
    }
    int wid = tid >> 5, lane = tid & 31;
    if (!lane) { red[wid] = s; red[4 + wid] = q; }
    __syncthreads();
    if (!tid) {
        float S = red[0] + red[1] + red[2] + red[3];
        float Q = red[4] + red[5] + red[6] + red[7];
        float mu = S / 512.f;
        float var = Q / 512.f - mu * mu;
        red[8] = mu;
        red[9] = rsqrtf(var + 1e-5f);
    }
    __syncthreads();
    float mu = red[8], rs = red[9];
    int k = tid * 4;
    row[k + 0] = (v.x - mu) * rs * lng[k + 0] + lnb[k + 0];
    row[k + 1] = (v.y - mu) * rs * lng[k + 1] + lnb[k + 1];
    row[k + 2] = (v.z - mu) * rs * lng[k + 2] + lnb[k + 2];
    row[k + 3] = (v.w - mu) * rs * lng[k + 3] + lnb[k + 3];
    __syncthreads();
    for (int o = wid; o < 22; o += 4) {
        float a = 0.f;
        const float* wr = wo + o * 512;
        for (int k2 = lane; k2 < 512; k2 += 32) a += row[k2] * wr[k2];
#pragma unroll
        for (int off = 16; off; off >>= 1) a += __shfl_xor_sync(0xffffffffu, a, off);
        if (!lane) g_feats[(size_t)i * 22 + o] = a + bo[o];
    }
}

// ---------------- CRF forward + scores (one warp per batch) -------------------
__global__ void crf_k(const float* __restrict__ trans, const int* __restrict__ mask,
                      const int* __restrict__ tags) {
    __shared__ float tr[484];
    __shared__ float alpha[22];
    int b = blockIdx.x, j = threadIdx.x;
    for (int q = j; q < 484; q += 32) tr[q] = trans[q];
    const float* Fb = g_feats + (size_t)b * 256 * 22;
    __syncwarp();
    if (j < 22) alpha[j] = tr[20 * 22 + j] + Fb[j];
    __syncwarp();
    for (int t = 1; t < 256; ++t) {
        float aj = 0.f;
        if (j < 22) {
            float m = -1e30f;
#pragma unroll
            for (int i2 = 0; i2 < 22; ++i2) m = fmaxf(m, alpha[i2] + tr[i2 * 22 + j]);
            float sm = 0.f;
#pragma unroll
            for (int i2 = 0; i2 < 22; ++i2) sm += expf(alpha[i2] + tr[i2 * 22 + j] - m);
            aj = m + logf(sm) + Fb[t * 22 + j];
        }
        int mt = mask[b * 256 + t];
        __syncwarp();
        if (j < 22 && mt) alpha[j] = aj;
        __syncwarp();
    }
    float v = (j < 22) ? alpha[j] + tr[j * 22 + 21] : -1e30f;
    float m = v;
#pragma unroll
    for (int off = 16; off; off >>= 1) m = fmaxf(m, __shfl_xor_sync(0xffffffffu, m, off));
    float e = (j < 22) ? expf(v - m) : 0.f;
#pragma unroll
    for (int off = 16; off; off >>= 1) e += __shfl_xor_sync(0xffffffffu, e, off);
    float logZ = m + logf(e);

    const int* tg = tags + (size_t)b * 256;
    const int* mk = mask + b * 256;
    float emit = 0.f, trs = 0.f;
    int cnt = 0;
    for (int t = j; t < 256; t += 32) {
        if (mk[t]) {
            emit += Fb[t * 22 + tg[t]];
            cnt++;
            if (t >= 1) trs += tr[tg[t - 1] * 22 + tg[t]];
        }
    }
#pragma unroll
    for (int off = 16; off; off >>= 1) {
        emit += __shfl_xor_sync(0xffffffffu, emit, off);
        trs += __shfl_xor_sync(0xffffffffu, trs, off);
        cnt += __shfl_xor_sync(0xffffffffu, cnt, off);
    }
    if (!j) {
        trs += tr[20 * 22 + tg[0]];
        trs += tr[tg[cnt - 1] * 22 + 21];
        g_nll[b] = logZ - emit - trs;
    }
}

__global__ void reduce_nll(float* out) {
    int tid = threadIdx.x;  // 128
    float v = g_nll[tid];
#pragma unroll
    for (int off = 16; off; off >>= 1) v += __shfl_xor_sync(0xffffffffu, v, off);
    __shared__ float r[4];
    if (!(tid & 31)) r[tid >> 5] = v;
    __syncthreads();
    if (!tid) out[0] = (r[0] + r[1] + r[2] + r[3]) / 128.f;
}

// ---------------- launcher ----------------
extern "C" void kernel_launch(void* const* d_in, const int* in_sizes, int n_in,
                              void* d_out, int out_size) {
    const float* emb    = (const float*)d_in[0];
    const float* w_ih0  = (const float*)d_in[1];
    const float* w_hh0  = (const float*)d_in[2];
    const float* b_ih0  = (const float*)d_in[3];
    const float* b_hh0  = (const float*)d_in[4];
    const float* w_ih1  = (const float*)d_in[5];
    const float* w_hh1  = (const float*)d_in[6];
    const float* b_ih1  = (const float*)d_in[7];
    const float* b_hh1  = (const float*)d_in[8];
    const float* ln_g   = (const float*)d_in[9];
    const float* ln_b   = (const float*)d_in[10];
    const float* w_out  = (const float*)d_in[11];
    const float* b_out  = (const float*)d_in[12];
    const float* trans  = (const float*)d_in[13];
    const int* words    = (const int*)d_in[14];
    const int* mask     = (const int*)d_in[15];
    const int* tags     = (const int*)d_in[16];
    float* out = (float*)d_out;

    cudaFuncSetAttribute(lstm_persist, cudaFuncAttributeMaxDynamicSharedMemorySize, PERS_SMEM);

    embed_k<<<32768, 256>>>(emb, words);
    gemm_xg_k<256><<<dim3(32, 256), 256>>>(w_ih0, b_ih0, b_hh0);
    init_hc<<<512, 256>>>();
    lstm_persist<<<128, 256, PERS_SMEM>>>(w_hh0, 0);
    gemm_xg_k<512><<<dim3(32, 256), 256>>>(w_ih1, b_ih1, b_hh1);
    init_hc<<<512, 256>>>();
    lstm_persist<<<128, 256, PERS_SMEM>>>(w_hh1, 1);
    lnfeats<<<32768, 128>>>(ln_g, ln_b, w_out, b_out);
    crf_k<<<128, 32>>>(trans, mask, tags);
    reduce_nll<<<1, 128>>>(out);
}

// round 5
// speedup vs baseline: 1.6113x; 1.2659x over previous
#include <cuda_runtime.h>

typedef unsigned long long ULL;

__device__ __forceinline__ void fma2(ULL& d, ULL a, ULL b) {
    asm("fma.rn.f32x2 %0, %1, %2, %0;" : "+l"(d) : "l"(a), "l"(b));
}
__device__ __forceinline__ ULL f2add(ULL a, ULL b) {
    ULL d;
    asm("add.rn.f32x2 %0, %1, %2;" : "=l"(d) : "l"(a), "l"(b));
    return d;
}
__device__ __forceinline__ float f2sum(ULL v) {
    float x, y;
    asm("mov.b64 {%0,%1}, %2;" : "=f"(x), "=f"(y) : "l"(v));
    return x + y;
}
__device__ __forceinline__ float sigf(float x) { return 1.f / (1.f + expf(-x)); }

// ---------------- scratch (static device buffers; no allocation) -------------
__device__ float g_x[32768 * 256];          // embedded input
__device__ float g_xg[(size_t)32768 * 2048];// input-proj gates buffer (reused per layer)
__device__ float g_out0[32768 * 512];       // layer0 output
__device__ float g_out1[32768 * 512];       // layer1 output
__device__ float g_h[2 * 2 * 128 * 256];    // h ping-pong [ping][dir][b][k]
__device__ float g_feats[(size_t)32768 * 22];
__device__ float g_nll[128];
__device__ unsigned g_bar[8];               // group barriers (dir x bch)

// ---------------- embedding gather ----------------
__global__ void embed_k(const float* __restrict__ emb, const int* __restrict__ words) {
    int idx = blockIdx.x * 256 + threadIdx.x;
    int i = idx >> 8, e = idx & 255;
    int w = words[i];
    g_x[idx] = emb[(size_t)w * 256 + e];
}

// ---------------- input-projection GEMM (unchanged, passing) -----------------
template <int K>
__global__ void __launch_bounds__(256) gemm_xg_k(const float* __restrict__ W,
                                                 const float* __restrict__ bi,
                                                 const float* __restrict__ bh) {
    const float* A = (K == 256) ? g_x : g_out0;
    __shared__ float As[2][128][18];
    __shared__ float Ws[2][64][18];

    int tid = threadIdx.x;
    int ty = tid >> 4, tx = tid & 15;
    const float* Ab = A + (size_t)blockIdx.y * 128 * K;
    const float* Wb = W + (size_t)blockIdx.x * 64 * K;

    int arow = tid >> 1, acol = (tid & 1) * 8;
    int wrow = tid >> 2, wcol = (tid & 3) * 4;

    float4 a0, a1, w0;
    a0 = *(const float4*)(Ab + arow * K + acol);
    a1 = *(const float4*)(Ab + arow * K + acol + 4);
    w0 = *(const float4*)(Wb + wrow * K + wcol);
    *(float2*)&As[0][arow][acol + 0] = make_float2(a0.x, a0.y);
    *(float2*)&As[0][arow][acol + 2] = make_float2(a0.z, a0.w);
    *(float2*)&As[0][arow][acol + 4] = make_float2(a1.x, a1.y);
    *(float2*)&As[0][arow][acol + 6] = make_float2(a1.z, a1.w);
    *(float2*)&Ws[0][wrow][wcol + 0] = make_float2(w0.x, w0.y);
    *(float2*)&Ws[0][wrow][wcol + 2] = make_float2(w0.z, w0.w);
    __syncthreads();

    ULL acc[8][4] = {};
    const int NC = K / 16;

    for (int c = 0; c < NC; ++c) {
        int buf = c & 1;
        if (c + 1 < NC) {
            const float* Ap = Ab + arow * K + (c + 1) * 16 + acol;
            a0 = *(const float4*)(Ap);
            a1 = *(const float4*)(Ap + 4);
            w0 = *(const float4*)(Wb + wrow * K + (c + 1) * 16 + wcol);
        }
#pragma unroll
        for (int kp = 0; kp < 8; ++kp) {
            ULL av[8], wv[4];
#pragma unroll
            for (int i = 0; i < 8; ++i) av[i] = *(const ULL*)&As[buf][ty * 8 + i][kp * 2];
#pragma unroll
            for (int j = 0; j < 4; ++j) wv[j] = *(const ULL*)&Ws[buf][tx + j * 16][kp * 2];
#pragma unroll
            for (int i = 0; i < 8; ++i)
#pragma unroll
                for (int j = 0; j < 4; ++j) fma2(acc[i][j], av[i], wv[j]);
        }
        if (c + 1 < NC) {
            int nb = buf ^ 1;
            *(float2*)&As[nb][arow][acol + 0] = make_float2(a0.x, a0.y);
            *(float2*)&As[nb][arow][acol + 2] = make_float2(a0.z, a0.w);
            *(float2*)&As[nb][arow][acol + 4] = make_float2(a1.x, a1.y);
            *(float2*)&As[nb][arow][acol + 6] = make_float2(a1.z, a1.w);
            *(float2*)&Ws[nb][wrow][wcol + 0] = make_float2(w0.x, w0.y);
            *(float2*)&Ws[nb][wrow][wcol + 2] = make_float2(w0.z, w0.w);
            __syncthreads();
        }
    }

#pragma unroll
    for (int i = 0; i < 8; ++i) {
        size_t m = (size_t)blockIdx.y * 128 + ty * 8 + i;
#pragma unroll
        for (int j = 0; j < 4; ++j) {
            int n = blockIdx.x * 64 + tx + j * 16;
            g_xg[m * 2048 + n] = f2sum(acc[i][j]) + bi[n] + bh[n];
        }
    }
}

// ---------------- zero h pings + group barriers ----------------
__global__ void init_hc() {
    int i = blockIdx.x * 256 + threadIdx.x;   // 512*256 = 131072 = all of g_h
    g_h[i] = 0.f;
    if (i < 8) g_bar[i] = 0u;
}

// ---------------- persistent BiLSTM layer v2 ----------------------------------
// 128 blocks: dir(2) x bch(4 of 32 batches) x uch(16 of 16 units); all resident.
// 512 threads: wg = tid>>7 splits K 4 ways (64 k each); wtid = tid&127:
//   u = wtid&15 (unit), bg = wtid>>4 (8 groups x 4 batches).
// W_hh slice staged once; c in registers; xg prefetched per step before compute;
// barrier: atomicAdd arrive + volatile-load poll (no RMW contention).
#define PERS_SMEM ((64 * 258 + 32 * 258) * 4 + 3 * 128 * 17 * 8)
__global__ void __launch_bounds__(512) lstm_persist(const float* __restrict__ whh, int layer) {
    extern __shared__ float sm[];
    float* ws = sm;                       // [64][258] rows: g*16+u
    float* hs = sm + 64 * 258;            // [32][258]
    ULL* part = (ULL*)(sm + 96 * 258);    // [3][128][17] partials from wg 1..3

    int bx = blockIdx.x;
    int dir = bx & 1, bch = (bx >> 1) & 3, uch = bx >> 3;
    int grp = bx & 7;
    int tid = threadIdx.x;
    int wg = tid >> 7, wtid = tid & 127;
    int u = wtid & 15, bg = wtid >> 4;
    int uu = uch * 16 + u;
    int b0 = bch * 32 + bg * 4;

    // stage W_hh slice once: 64 rows x 256 k = 8192 float2, 16 per thread
    const float* wb = whh + (size_t)dir * 1024 * 256;
#pragma unroll 4
    for (int r = 0; r < 16; ++r) {
        int q = r * 512 + tid;
        int wrow = q >> 7, cc = q & 127;
        int gt = wrow >> 4, uw = wrow & 15;
        *(float2*)&ws[wrow * 258 + cc * 2] =
            *(const float2*)&wb[(size_t)(gt * 256 + uch * 16 + uw) * 256 + cc * 2];
    }

    float creg[4] = {0.f, 0.f, 0.f, 0.f};
    float* ob = layer ? g_out1 : g_out0;
    const int kbase = wg * 64;

    for (int t = 0; t < 256; ++t) {
        int td = dir ? 255 - t : t;
        const float* hin = g_h + (t & 1) * (2 * 128 * 256);
        float* hout = g_h + ((t & 1) ^ 1) * (2 * 128 * 256);

        // prefetch gate biases for this step (DRAM latency hides under staging+MMA)
        float xg[16];
        if (wg == 0) {
#pragma unroll
            for (int j = 0; j < 4; ++j) {
                size_t xb = ((size_t)(b0 + j) * 256 + td) * 2048 + dir * 1024 + uu;
                xg[j * 4 + 0] = __ldcg(&g_xg[xb]);
                xg[j * 4 + 1] = __ldcg(&g_xg[xb + 256]);
                xg[j * 4 + 2] = __ldcg(&g_xg[xb + 512]);
                xg[j * 4 + 3] = __ldcg(&g_xg[xb + 768]);
            }
        }

        // stage h_{t-1}: 4096 float2, 8 per thread (.cg bypasses stale L1)
        const float* hb = hin + (dir * 128 + bch * 32) * 256;
#pragma unroll
        for (int r = 0; r < 8; ++r) {
            int q = r * 512 + tid;
            int row = q >> 7, cc = q & 127;
            *(float2*)&hs[row * 258 + cc * 2] = __ldcg((const float2*)&hb[row * 256 + cc * 2]);
        }
        __syncthreads();

        ULL acc[4][4] = {};
#pragma unroll 8
        for (int kp = 0; kp < 32; ++kp) {
            ULL hv[4], wv[4];
#pragma unroll
            for (int j = 0; j < 4; ++j)
                hv[j] = *(const ULL*)&hs[(bg * 4 + j) * 258 + kbase + kp * 2];
#pragma unroll
            for (int g = 0; g < 4; ++g)
                wv[g] = *(const ULL*)&ws[(g * 16 + u) * 258 + kbase + kp * 2];
#pragma unroll
            for (int g = 0; g < 4; ++g)
#pragma unroll
                for (int j = 0; j < 4; ++j) fma2(acc[g][j], hv[j], wv[g]);
        }

        if (wg) {
            ULL* pp = &part[((wg - 1) * 128 + wtid) * 17];
#pragma unroll
            for (int g = 0; g < 4; ++g)
#pragma unroll
                for (int j = 0; j < 4; ++j) pp[g * 4 + j] = acc[g][j];
        }
        __syncthreads();

        if (wg == 0) {
#pragma unroll
            for (int j = 0; j < 4; ++j) {
                int b = b0 + j;
                float gv[4];
#pragma unroll
                for (int g = 0; g < 4; ++g) {
                    ULL s = acc[g][j];
#pragma unroll
                    for (int w = 0; w < 3; ++w)
                        s = f2add(s, part[(w * 128 + wtid) * 17 + g * 4 + j]);
                    gv[g] = f2sum(s) + xg[j * 4 + g];
                }
                float cn = sigf(gv[1]) * creg[j] + sigf(gv[0]) * tanhf(gv[2]);
                float hn = sigf(gv[3]) * tanhf(cn);
                creg[j] = cn;
                hout[(dir * 128 + b) * 256 + uu] = hn;
                ob[((size_t)b * 256 + td) * 512 + dir * 256 + uu] = hn;
            }
            __threadfence();
        }
        __syncthreads();

        // group barrier: 16 blocks of (dir,bch); arrive once, poll via plain L2 load
        if (tid == 0) {
            atomicAdd(&g_bar[grp], 1u);
            unsigned tgt = 16u * (unsigned)(t + 1);
            volatile unsigned* p = &g_bar[grp];
            while (*p < tgt) __nanosleep(32);
            __threadfence();
        }
        __syncthreads();
    }
}

// ---------------- LayerNorm + output projection -------------------------------
__global__ void __launch_bounds__(128) lnfeats(const float* __restrict__ lng,
                                               const float* __restrict__ lnb,
                                               const float* __restrict__ wo,
                                               const float* __restrict__ bo) {
    __shared__ float row[512];
    __shared__ float red[10];
    int i = blockIdx.x, tid = threadIdx.x;
    float4 v = *(const float4*)&g_out1[(size_t)i * 512 + tid * 4];
    float s = v.x + v.y + v.z + v.w;
    float q = v.x * v.x + v.y * v.y + v.z * v.z + v.w * v.w;
#pragma unroll
    for (int o = 16; o; o >>= 1) {
        s += __shfl_xor_sync(0xffffffffu, s, o);
        q += __shfl_xor_sync(0xffffffffu, q, o);
    }
    int wid = tid >> 5, lane = tid & 31;
    if (!lane) { red[wid] = s; red[4 + wid] = q; }
    __syncthreads();
    if (!tid) {
        float S = red[0] + red[1] + red[2] + red[3];
        float Q = red[4] + red[5] + red[6] + red[7];
        float mu = S / 512.f;
        float var = Q / 512.f - mu * mu;
        red[8] = mu;
        red[9] = rsqrtf(var + 1e-5f);
    }
    __syncthreads();
    float mu = red[8], rs = red[9];
    int k = tid * 4;
    row[k + 0] = (v.x - mu) * rs * lng[k + 0] + lnb[k + 0];
    row[k + 1] = (v.y - mu) * rs * lng[k + 1] + lnb[k + 1];
    row[k + 2] = (v.z - mu) * rs * lng[k + 2] + lnb[k + 2];
    row[k + 3] = (v.w - mu) * rs * lng[k + 3] + lnb[k + 3];
    __syncthreads();
    for (int o = wid; o < 22; o += 4) {
        float a = 0.f;
        const float* wr = wo + o * 512;
        for (int k2 = lane; k2 < 512; k2 += 32) a += row[k2] * wr[k2];
#pragma unroll
        for (int off = 16; off; off >>= 1) a += __shfl_xor_sync(0xffffffffu, a, off);
        if (!lane) g_feats[(size_t)i * 22 + o] = a + bo[o];
    }
}

// ---------------- CRF forward + scores (one warp per batch) -------------------
__global__ void crf_k(const float* __restrict__ trans, const int* __restrict__ mask,
                      const int* __restrict__ tags) {
    __shared__ float tr[484];
    __shared__ float alpha[22];
    int b = blockIdx.x, j = threadIdx.x;
    for (int q = j; q < 484; q += 32) tr[q] = trans[q];
    const float* Fb = g_feats + (size_t)b * 256 * 22;
    __syncwarp();
    if (j < 22) alpha[j] = tr[20 * 22 + j] + Fb[j];
    __syncwarp();
    for (int t = 1; t < 256; ++t) {
        float aj = 0.f;
        if (j < 22) {
            float m = -1e30f;
#pragma unroll
            for (int i2 = 0; i2 < 22; ++i2) m = fmaxf(m, alpha[i2] + tr[i2 * 22 + j]);
            float sm = 0.f;
#pragma unroll
            for (int i2 = 0; i2 < 22; ++i2) sm += expf(alpha[i2] + tr[i2 * 22 + j] - m);
            aj = m + logf(sm) + Fb[t * 22 + j];
        }
        int mt = mask[b * 256 + t];
        __syncwarp();
        if (j < 22 && mt) alpha[j] = aj;
        __syncwarp();
    }
    float v = (j < 22) ? alpha[j] + tr[j * 22 + 21] : -1e30f;
    float m = v;
#pragma unroll
    for (int off = 16; off; off >>= 1) m = fmaxf(m, __shfl_xor_sync(0xffffffffu, m, off));
    float e = (j < 22) ? expf(v - m) : 0.f;
#pragma unroll
    for (int off = 16; off; off >>= 1) e += __shfl_xor_sync(0xffffffffu, e, off);
    float logZ = m + logf(e);

    const int* tg = tags + (size_t)b * 256;
    const int* mk = mask + b * 256;
    float emit = 0.f, trs = 0.f;
    int cnt = 0;
    for (int t = j; t < 256; t += 32) {
        if (mk[t]) {
            emit += Fb[t * 22 + tg[t]];
            cnt++;
            if (t >= 1) trs += tr[tg[t - 1] * 22 + tg[t]];
        }
    }
#pragma unroll
    for (int off = 16; off; off >>= 1) {
        emit += __shfl_xor_sync(0xffffffffu, emit, off);
        trs += __shfl_xor_sync(0xffffffffu, trs, off);
        cnt += __shfl_xor_sync(0xffffffffu, cnt, off);
    }
    if (!j) {
        trs += tr[20 * 22 + tg[0]];
        trs += tr[tg[cnt - 1] * 22 + 21];
        g_nll[b] = logZ - emit - trs;
    }
}

__global__ void reduce_nll(float* out) {
    int tid = threadIdx.x;  // 128
    float v = g_nll[tid];
#pragma unroll
    for (int off = 16; off; off >>= 1) v += __shfl_xor_sync(0xffffffffu, v, off);
    __shared__ float r[4];
    if (!(tid & 31)) r[tid >> 5] = v;
    __syncthreads();
    if (!tid) out[0] = (r[0] + r[1] + r[2] + r[3]) / 128.f;
}

// ---------------- launcher ----------------
extern "C" void kernel_launch(void* const* d_in, const int* in_sizes, int n_in,
                              void* d_out, int out_size) {
    const float* emb    = (const float*)d_in[0];
    const float* w_ih0  = (const float*)d_in[1];
    const float* w_hh0  = (const float*)d_in[2];
    const float* b_ih0  = (const float*)d_in[3];
    const float* b_hh0  = (const float*)d_in[4];
    const float* w_ih1  = (const float*)d_in[5];
    const float* w_hh1  = (const float*)d_in[6];
    const float* b_ih1  = (const float*)d_in[7];
    const float* b_hh1  = (const float*)d_in[8];
    const float* ln_g   = (const float*)d_in[9];
    const float* ln_b   = (const float*)d_in[10];
    const float* w_out  = (const float*)d_in[11];
    const float* b_out  = (const float*)d_in[12];
    const float* trans  = (const float*)d_in[13];
    const int* words    = (const int*)d_in[14];
    const int* mask     = (const int*)d_in[15];
    const int* tags     = (const int*)d_in[16];
    float* out = (float*)d_out;

    cudaFuncSetAttribute(lstm_persist, cudaFuncAttributeMaxDynamicSharedMemorySize, PERS_SMEM);

    embed_k<<<32768, 256>>>(emb, words);
    gemm_xg_k<256><<<dim3(32, 256), 256>>>(w_ih0, b_ih0, b_hh0);
    init_hc<<<512, 256>>>();
    lstm_persist<<<128, 512, PERS_SMEM>>>(w_hh0, 0);
    gemm_xg_k<512><<<dim3(32, 256), 256>>>(w_ih1, b_ih1, b_hh1);
    init_hc<<<512, 256>>>();
    lstm_persist<<<128, 512, PERS_SMEM>>>(w_hh1, 1);
    lnfeats<<<32768, 128>>>(ln_g, ln_b, w_out, b_out);
    crf_k<<<128, 32>>>(trans, mask, tags);
    reduce_nll<<<1, 128>>>(out);
}